// round 3
// baseline (speedup 1.0000x reference)
#include <cuda_runtime.h>
#include <cuda_bf16.h>
#include <math.h>

// ---------------------------------------------------------------------------
// CFGGraphEncoder: 3-layer GCN-style encoder.
//   layer(x): agg = segment_sum(x[cols], rows); y = tanh((agg + 2x) @ W + b)
//   out = concat([x1, x2, x3], axis=1)  [N, 96]  ++  bincount(batch, 64)
//
// NOTE: edge_index / batch_indices are int32 on device (JAX default x64 off).
// ---------------------------------------------------------------------------

#define N_MAX 131072
#define E_MAX 1700000
#define SCAN_BLK 1024
#define MAX_SCAN_BLOCKS 256   // N_MAX / SCAN_BLK = 128 <= 256

__device__ int   g_cursor[N_MAX];       // deg during histogram, then write cursor
__device__ int   g_off[N_MAX + 1];      // CSR row offsets
__device__ int   g_csr[E_MAX];          // CSR column indices
__device__ int   g_blocksum[MAX_SCAN_BLOCKS];
__device__ int   g_blockoff[MAX_SCAN_BLOCKS];
__device__ int   g_hist[64];
__device__ float g_x1[N_MAX * 32];
__device__ float g_x2[N_MAX * 32];

// ---------------------------------------------------------------------------
// Block-wide exclusive scan (blockDim.x multiple of 32, <= 1024).
// ---------------------------------------------------------------------------
__device__ __forceinline__ int block_scan_excl(int v, int* p_total) {
    __shared__ int s_warp[32];
    __shared__ int s_tot;
    const unsigned FULL = 0xffffffffu;
    int lane = threadIdx.x & 31;
    int wid  = threadIdx.x >> 5;
    int nw   = blockDim.x >> 5;

    int incl = v;
#pragma unroll
    for (int d = 1; d < 32; d <<= 1) {
        int t = __shfl_up_sync(FULL, incl, d);
        if (lane >= d) incl += t;
    }
    if (lane == 31) s_warp[wid] = incl;
    __syncthreads();
    if (wid == 0) {
        int wv = (lane < nw) ? s_warp[lane] : 0;
        int wincl = wv;
#pragma unroll
        for (int d = 1; d < 32; d <<= 1) {
            int t = __shfl_up_sync(FULL, wincl, d);
            if (lane >= d) wincl += t;
        }
        if (lane == nw - 1) s_tot = wincl;
        s_warp[lane] = wincl - wv;   // exclusive warp offset
    }
    __syncthreads();
    *p_total = s_tot;
    return (incl - v) + s_warp[wid];
}

// ---------------------------------------------------------------------------
// Setup kernels
// ---------------------------------------------------------------------------
__global__ void k_zero(int N) {
    int i = blockIdx.x * blockDim.x + threadIdx.x;
    if (i < N) g_cursor[i] = 0;
    if (i < 64) g_hist[i] = 0;
}

__global__ void k_deg(const int* __restrict__ ei, int E) {
    int e = blockIdx.x * blockDim.x + threadIdx.x;
    if (e < E) {
        int r = ei[e];               // rows = ei[0, :]
        atomicAdd(&g_cursor[r], 1);
    }
}

__global__ void k_blocktot(int N) {
    int n = blockIdx.x * blockDim.x + threadIdx.x;
    int v = (n < N) ? g_cursor[n] : 0;
    int tot;
    (void)block_scan_excl(v, &tot);
    if (threadIdx.x == 0) g_blocksum[blockIdx.x] = tot;
}

__global__ void k_scanblocks(int nblocks) {
    int t = threadIdx.x;                 // blockDim = 128 >= nblocks
    int v = (t < nblocks) ? g_blocksum[t] : 0;
    int tot;
    int excl = block_scan_excl(v, &tot);
    if (t < nblocks) g_blockoff[t] = excl;
}

__global__ void k_scanapply(int N) {
    int n = blockIdx.x * blockDim.x + threadIdx.x;
    int v = (n < N) ? g_cursor[n] : 0;
    int tot;
    int excl = block_scan_excl(v, &tot);
    int offv = g_blockoff[blockIdx.x] + excl;
    if (n < N) {
        g_off[n]    = offv;
        g_cursor[n] = offv;   // cursor for the scatter pass
    }
    if (n == N - 1) g_off[N] = offv + v;
}

__global__ void k_scatter(const int* __restrict__ ei, int E) {
    int e = blockIdx.x * blockDim.x + threadIdx.x;
    if (e < E) {
        int r = ei[e];
        int c = ei[E + e];               // cols = ei[1, :]
        int pos = atomicAdd(&g_cursor[r], 1);
        g_csr[pos] = c;
    }
}

__global__ void k_bhist(const int* __restrict__ bi, int N) {
    __shared__ int sh[64];
    if (threadIdx.x < 64) sh[threadIdx.x] = 0;
    __syncthreads();
    int i = blockIdx.x * blockDim.x + threadIdx.x;
    if (i < N) atomicAdd(&sh[bi[i]], 1);
    __syncthreads();
    if (threadIdx.x < 64 && sh[threadIdx.x] != 0)
        atomicAdd(&g_hist[threadIdx.x], sh[threadIdx.x]);
}

__global__ void k_sizes(float* __restrict__ out_tail) {
    int t = threadIdx.x;
    if (t < 64) out_tail[t] = (float)g_hist[t];
}

// ---------------------------------------------------------------------------
// Fused layer: one warp per node, lane = input feature.
// ---------------------------------------------------------------------------
#define WARPS_PER_BLOCK 8

template <int FIN, int SRC, int DST>
__global__ __launch_bounds__(WARPS_PER_BLOCK * 32)
void k_layer(const float* __restrict__ x0,
             const float* __restrict__ W,   // [FIN, 32] row-major
             const float* __restrict__ b,   // [32]
             float* __restrict__ out96,     // [N, 96]
             int N, int col_ofs) {
    __shared__ float Ws[FIN * 32];
    __shared__ float bs[32];

    for (int i = threadIdx.x; i < FIN * 32; i += blockDim.x) Ws[i] = W[i];
    if (threadIdx.x < 32) bs[threadIdx.x] = b[threadIdx.x];
    __syncthreads();

    const float* __restrict__ x_in =
        (SRC == 0) ? x0 : ((SRC == 1) ? (const float*)g_x1 : (const float*)g_x2);

    int warp = threadIdx.x >> 5;
    int lane = threadIdx.x & 31;
    int n = blockIdx.x * WARPS_PER_BLOCK + warp;
    if (n >= N) return;

    const unsigned FULL = 0xffffffffu;

    float s = 0.0f;
    if (lane < FIN) s = 2.0f * __ldg(&x_in[(long long)n * FIN + lane]);

    int start = g_off[n];
    int end   = g_off[n + 1];

    for (int base = start; base < end; base += 32) {
        int idx = 0;
        if (base + lane < end) idx = g_csr[base + lane];
        int cnt = min(32, end - base);
        for (int j = 0; j < cnt; j++) {
            int c = __shfl_sync(FULL, idx, j);
            if (lane < FIN) s += __ldg(&x_in[(long long)c * FIN + lane]);
        }
    }

    // 32-wide GEMM via shuffle broadcast of s
    float acc = bs[lane];
#pragma unroll
    for (int f = 0; f < FIN; f++) {
        float af = __shfl_sync(FULL, s, f);
        acc = fmaf(af, Ws[f * 32 + lane], acc);
    }
    float y = tanhf(acc);

    if (DST == 1) g_x1[(long long)n * 32 + lane] = y;
    if (DST == 2) g_x2[(long long)n * 32 + lane] = y;
    out96[(long long)n * 96 + col_ofs + lane] = y;
}

// ---------------------------------------------------------------------------
// Launch
// ---------------------------------------------------------------------------
extern "C" void kernel_launch(void* const* d_in, const int* in_sizes, int n_in,
                              void* d_out, int out_size) {
    const float* x0 = (const float*)d_in[0];      // [N, 11]
    const int*   ei = (const int*)d_in[1];        // [2, E] int32
    const int*   bi = (const int*)d_in[2];        // [N]    int32
    const float* W1 = (const float*)d_in[3];
    const float* b1 = (const float*)d_in[4];
    const float* W2 = (const float*)d_in[5];
    const float* b2 = (const float*)d_in[6];
    const float* W3 = (const float*)d_in[7];
    const float* b3 = (const float*)d_in[8];
    float* out = (float*)d_out;

    int N = in_sizes[0] / 11;
    int E = in_sizes[1] / 2;
    int tail = out_size - 64;

    int zb = (max(N, 64) + 255) / 256;
    k_zero<<<zb, 256>>>(N);

    int eb = (E + 255) / 256;
    k_deg<<<eb, 256>>>(ei, E);

    int nb = (N + SCAN_BLK - 1) / SCAN_BLK;
    k_blocktot<<<nb, SCAN_BLK>>>(N);
    k_scanblocks<<<1, 128>>>(nb);
    k_scanapply<<<nb, SCAN_BLK>>>(N);

    k_scatter<<<eb, 256>>>(ei, E);

    k_bhist<<<(N + 255) / 256, 256>>>(bi, N);
    k_sizes<<<1, 64>>>(out + tail);

    int lb = (N + WARPS_PER_BLOCK - 1) / WARPS_PER_BLOCK;
    k_layer<11, 0, 1><<<lb, WARPS_PER_BLOCK * 32>>>(x0, W1, b1, out, N, 0);
    k_layer<32, 1, 2><<<lb, WARPS_PER_BLOCK * 32>>>(x0, W2, b2, out, N, 32);
    k_layer<32, 2, 0><<<lb, WARPS_PER_BLOCK * 32>>>(x0, W3, b3, out, N, 64);
}